// round 14
// baseline (speedup 1.0000x reference)
#include <cuda_runtime.h>

#define B 4
#define C 32
#define H 256
#define W 256
#define H3 768
#define W3 768
#define PLANE_IN  65536
#define PLANE_OUT 589824
#define SMROW 272              // skewed row: skew(260)=268 -> pad 272
#define STRIP 16               // input row-groups per block
#define SROWS (STRIP + 2)      // 18 staged input rows
#define NTHR 288               // (96 chunks) x (3 kx); 18*32 = 576 = 2*288

__device__ __forceinline__ int skew(int i) { return i + (i >> 5); }

// 32-byte evict_last load
__device__ __forceinline__ void ldg_el_8f(const float* p, float* v) {
    unsigned long long a, b, c, d;
    asm("ld.global.nc.L2::evict_last.v4.b64 {%0,%1,%2,%3}, [%4];"
        : "=l"(a), "=l"(b), "=l"(c), "=l"(d) : "l"(p));
    *reinterpret_cast<unsigned long long*>(v + 0) = a;
    *reinterpret_cast<unsigned long long*>(v + 2) = b;
    *reinterpret_cast<unsigned long long*>(v + 4) = c;
    *reinterpret_cast<unsigned long long*>(v + 6) = d;
}

// 32-byte evict_first store
__device__ __forceinline__ void stg_ef_8f(float* p, const float* v) {
    const unsigned long long a = *reinterpret_cast<const unsigned long long*>(v + 0);
    const unsigned long long b = *reinterpret_cast<const unsigned long long*>(v + 2);
    const unsigned long long c = *reinterpret_cast<const unsigned long long*>(v + 4);
    const unsigned long long d = *reinterpret_cast<const unsigned long long*>(v + 6);
    asm volatile("st.global.L2::evict_first.v4.b64 [%0], {%1,%2,%3,%4};"
                 :: "l"(p), "l"(a), "l"(b), "l"(c), "l"(d) : "memory");
}

// out[p, I, J] = x[p, reflect(I/3+I%3-1), reflect(J/3+J%3-1)]
//                * (I==767?2:1) * (J==767?2:1)
__global__ __launch_bounds__(NTHR)
void deform_w32s16_kernel(const float* __restrict__ x, float* __restrict__ out) {
    __shared__ float sm[SROWS][SMROW];

    const int tid   = threadIdx.x;
    const int base  = blockIdx.x * STRIP;
    const int plane = blockIdx.y;

    const float* __restrict__ xp = x + (size_t)plane * PLANE_IN;

    // ---- stage SROWS reflected rows: 576 32B-chunks = exactly 2 passes ----
#pragma unroll
    for (int k = 0; k < 2; ++k) {
        const int idx = tid + NTHR * k;     // 0..575
        const int s  = idx >> 5;            // smem row 0..17
        const int c8 = idx & 31;            // 8-float chunk
        int ri = base - 1 + s;
        ri = (ri < 0) ? 1 : ((ri > H - 1) ? H - 2 : ri);
        float v[8];
        ldg_el_8f(xp + ri * W + 8 * c8, v);
        float* r = sm[s];
        const int b0 = 8 * c8 + 4;
#pragma unroll
        for (int e = 0; e < 8; ++e)
            r[skew(b0 + e)] = v[e];
        if (c8 == 0)  r[3]   = v[1];        // col -1  -> x[1]
        if (c8 == 31) r[268] = v[6];        // col 256 -> x[254]
    }
    __syncthreads();

    // ---- compute: thread = (c8, kx); 8 outputs per row, one 32B store ----
    const int c8 = tid % 96;                // output 8-float chunk in row
    const int kx = tid / 96;                // 0..2
    const int J0 = 8 * c8;

    // smem indices for the 8 output columns (reused across all groups)
    int sidx[8];
#pragma unroll
    for (int e = 0; e < 8; ++e) {
        const int J = J0 + e;
        int c = (J + 2 * (J % 3)) / 3 - 1;  // input col = J/3 + J%3 - 1
        if (c < 0)     c = 1;               // J=0:   col -1  -> x[1]
        if (c > W - 1) c = W - 2;           // J=767: col 256 -> x[254]
        sidx[e] = skew(c + 4);
    }
    const float wlast = (c8 == 95) ? 2.0f : 1.0f;   // J=767 weight (e==7)

    float* __restrict__ opl = out + (size_t)plane * PLANE_OUT;

#pragma unroll
    for (int g = 0; g < STRIP; ++g) {
        const int ig = base + g;
        const float* r = sm[g + kx];        // input row for out row 3*ig+kx
        float v[8];
#pragma unroll
        for (int e = 0; e < 8; ++e)
            v[e] = r[sidx[e]];
        if (kx == 2 && ig == H - 1) {       // output row I=767: weight 2
#pragma unroll
            for (int e = 0; e < 8; ++e)
                v[e] *= 2.0f;
        }
        v[7] *= wlast;                      // output col J=767: weight 2
        stg_ef_8f(opl + (size_t)(3 * ig + kx) * W3 + J0, v);
    }
}

extern "C" void kernel_launch(void* const* d_in, const int* in_sizes, int n_in,
                              void* d_out, int out_size) {
    const float* x = (const float*)d_in[0];
    float* out = (float*)d_out;
    (void)in_sizes; (void)n_in; (void)out_size;

    dim3 grid(H / STRIP, B * C);   // 16 x 128 = 2048 blocks
    deform_w32s16_kernel<<<grid, NTHR>>>(x, out);
}

// round 15
// speedup vs baseline: 1.0317x; 1.0317x over previous
#include <cuda_runtime.h>

#define B 4
#define C 32
#define H 256
#define W 256
#define H3 768
#define W3 768
#define PLANE_IN  65536
#define PLANE_OUT 589824
#define SMROW 272              // skewed row: skew(260)=268 -> pad 272
#define STRIP 8                // input row-groups per block
#define SROWS (STRIP + 2)      // 10 staged input rows
#define NTHR 288               // (96 chunks) x (3 kx)

__device__ __forceinline__ int skew(int i) { return i + (i >> 5); }

// 32-byte evict_last load
__device__ __forceinline__ void ldg_el_8f(const float* p, float* v) {
    unsigned long long a, b, c, d;
    asm("ld.global.nc.L2::evict_last.v4.b64 {%0,%1,%2,%3}, [%4];"
        : "=l"(a), "=l"(b), "=l"(c), "=l"(d) : "l"(p));
    *reinterpret_cast<unsigned long long*>(v + 0) = a;
    *reinterpret_cast<unsigned long long*>(v + 2) = b;
    *reinterpret_cast<unsigned long long*>(v + 4) = c;
    *reinterpret_cast<unsigned long long*>(v + 6) = d;
}

// 32-byte evict_first store
__device__ __forceinline__ void stg_ef_8f(float* p, const float* v) {
    const unsigned long long a = *reinterpret_cast<const unsigned long long*>(v + 0);
    const unsigned long long b = *reinterpret_cast<const unsigned long long*>(v + 2);
    const unsigned long long c = *reinterpret_cast<const unsigned long long*>(v + 4);
    const unsigned long long d = *reinterpret_cast<const unsigned long long*>(v + 6);
    asm volatile("st.global.L2::evict_first.v4.b64 [%0], {%1,%2,%3,%4};"
                 :: "l"(p), "l"(a), "l"(b), "l"(c), "l"(d) : "memory");
}

// out[p, I, J] = x[p, reflect(I/3+I%3-1), reflect(J/3+J%3-1)]
//                * (I==767?2:1) * (J==767?2:1)
__global__ __launch_bounds__(NTHR)
void deform_w32sel_kernel(const float* __restrict__ x, float* __restrict__ out) {
    __shared__ float sm[SROWS][SMROW];

    const int tid   = threadIdx.x;
    const int base  = blockIdx.x * STRIP;
    const int plane = blockIdx.y;

    const float* __restrict__ xp = x + (size_t)plane * PLANE_IN;

    // ---- stage SROWS reflected rows: 320 32B-chunks, 288 threads, 2 passes ----
#pragma unroll
    for (int k = 0; k < 2; ++k) {
        const int idx = tid + NTHR * k;
        if (idx < SROWS * 32) {
            const int s  = idx >> 5;        // smem row 0..9
            const int c8 = idx & 31;        // 8-float chunk
            int ri = base - 1 + s;
            ri = (ri < 0) ? 1 : ((ri > H - 1) ? H - 2 : ri);
            float v[8];
            ldg_el_8f(xp + ri * W + 8 * c8, v);
            float* r = sm[s];
            const int b0 = 8 * c8 + 4;
#pragma unroll
            for (int e = 0; e < 8; ++e)
                r[skew(b0 + e)] = v[e];
            if (c8 == 0)  r[3]   = v[1];    // col -1  -> x[1]   (skew(3)==3)
            if (c8 == 31) r[268] = v[6];    // col 256 -> x[254] (skew(260))
        }
    }
    __syncthreads();

    // ---- compute: thread = (c8, kx); 4 LDS + selects -> one 32B store ----
    const int c8 = tid % 96;                // output 8-float chunk in row
    const int kx = tid / 96;                // 0..2
    const int J0 = 8 * c8;

    // The 8 output cols J0..J0+7 gather from 4 consecutive input cols lo..lo+3,
    // with permutation selected by r = J0 mod 3:
    //   r=0: {0,1,2,1,2,3,2,3}  r=1: {0,1,0,1,2,1,2,3}  r=2: {1,0,1,2,1,2,3,2}
    const int  r3  = J0 % 3;
    const bool pr0 = (r3 == 0);
    const bool pr2 = (r3 == 2);
    const int  lo  = J0 / 3 - (pr0 ? 1 : 0);
    // smem idx for col c is skew(c+4); halos line up: col -1 -> 3, col 256 -> 268
    const int si0 = skew(lo + 4);
    const int si1 = skew(lo + 5);
    const int si2 = skew(lo + 6);
    const int si3 = skew(lo + 7);

    const float wlast = (c8 == 95) ? 2.0f : 1.0f;   // J=767 weight (e==7)

    float* __restrict__ opl = out + (size_t)plane * PLANE_OUT;

#pragma unroll
    for (int g = 0; g < STRIP; ++g) {
        const int ig = base + g;
        const float* r = sm[g + kx];        // input row for out row 3*ig+kx
        const float L0 = r[si0];
        const float L1 = r[si1];
        const float L2 = r[si2];
        const float L3 = r[si3];

        float v[8];
        v[0] = pr2 ? L1 : L0;
        v[1] = pr2 ? L0 : L1;
        v[2] = pr0 ? L2 : (pr2 ? L1 : L0);
        v[3] = pr2 ? L2 : L1;
        v[4] = pr2 ? L1 : L2;
        v[5] = pr0 ? L3 : (pr2 ? L2 : L1);
        v[6] = pr2 ? L3 : L2;
        v[7] = (pr2 ? L2 : L3) * wlast;     // J=767: weight 2

        if (kx == 2 && ig == H - 1) {       // output row I=767: weight 2
#pragma unroll
            for (int e = 0; e < 8; ++e)
                v[e] *= 2.0f;
        }
        stg_ef_8f(opl + (size_t)(3 * ig + kx) * W3 + J0, v);
    }
}

extern "C" void kernel_launch(void* const* d_in, const int* in_sizes, int n_in,
                              void* d_out, int out_size) {
    const float* x = (const float*)d_in[0];
    float* out = (float*)d_out;
    (void)in_sizes; (void)n_in; (void)out_size;

    dim3 grid(H / STRIP, B * C);   // 32 x 128 = 4096 blocks
    deform_w32sel_kernel<<<grid, NTHR>>>(x, out);
}